// round 15
// baseline (speedup 1.0000x reference)
#include <cuda_runtime.h>
#include <cuda.h>
#include <math.h>
#include <stdint.h>

#define T_FRAMES 16384
#define C        7
#define F_DIM    2048
#define LEN_Q    30
#define N_HEADS  4
#define D_FF     64

#define FPB      64                    // frames per block (GEMM M)
#define KC       32                    // K floats per TMA chunk (128 B rows)
#define CHUNKS   (F_DIM / KC)          // 64
#define NBUF     4                     // A-ring depth
#define CH_F     (FPB * KC)            // 2048 floats per A chunk (8 KB)
#define CH_BYTES (CH_F * 4)
#define ROWS     (FPB + LEN_Q - 1)     // 93
#define NSTR     33
#define NP_F     (ROWS * NSTR)         // 3069

#define THREADS  288                   // 8 compute warps + 1 producer warp
#define CWARPS   8

#define RING_F   (NBUF * CH_F)         // 8192 floats (32 KB)
#define DYN_BYTES (RING_F * 4 + 1024)

// ---- prep-kernel outputs ----
__device__ uint32_t g_Btf[F_DIM * 8];          // tf32(Wfc^T), n padded to 8
__device__ float    g_cA[N_HEADS * C * 8];     // A_h = Wq_h^T Wk_h
__device__ float    g_cB[N_HEADS * C * 8];     // B_h = Wo_h  Wv_h

__device__ __forceinline__ uint32_t smem_u32(const void* p) {
    uint32_t a;
    asm("{ .reg .u64 t; cvta.to.shared.u64 t, %1; cvt.u32.u64 %0, t; }"
        : "=r"(a) : "l"(p));
    return a;
}
__device__ __forceinline__ void mbar_init(uint32_t mbar, uint32_t cnt) {
    asm volatile("mbarrier.init.shared.b64 [%0], %1;" :: "r"(mbar), "r"(cnt) : "memory");
}
__device__ __forceinline__ void mbar_arrive(uint32_t mbar) {
    asm volatile("mbarrier.arrive.release.cta.shared::cta.b64 _, [%0];"
                 :: "r"(mbar) : "memory");
}
__device__ __forceinline__ void mbar_expect_tx(uint32_t mbar, uint32_t bytes) {
    asm volatile("mbarrier.arrive.expect_tx.shared.b64 _, [%0], %1;"
                 :: "r"(mbar), "r"(bytes) : "memory");
}
__device__ __forceinline__ void mbar_wait_parity(uint32_t mbar, uint32_t ph) {
    asm volatile(
        "{\n\t.reg .pred P;\n\t"
        "WAIT_%=:\n\t"
        "mbarrier.try_wait.parity.acquire.cta.shared::cta.b64 P, [%0], %1, 0x989680;\n\t"
        "@P bra.uni DONE_%=;\n\t"
        "bra.uni WAIT_%=;\n\t"
        "DONE_%=:\n\t}"
        :: "r"(mbar), "r"(ph) : "memory");
}
__device__ __forceinline__ void tma_2d(uint32_t dst, const void* tmap,
                                       int cx, int cy, uint32_t mbar) {
    asm volatile(
        "cp.async.bulk.tensor.2d.shared::cta.global.tile.mbarrier::complete_tx::bytes "
        "[%0], [%1, {%2, %3}], [%4];"
        :: "r"(dst), "l"(tmap), "r"(cx), "r"(cy), "r"(mbar) : "memory");
}
__device__ __forceinline__ uint32_t to_tf32(float f) {
    uint32_t r;
    asm("cvt.rna.tf32.f32 %0, %1;" : "=r"(r) : "f"(f));
    return r;
}
__device__ __forceinline__ void mma_tf32(float& c0, float& c1, float& c2, float& c3,
                                         uint32_t a0, uint32_t a1, uint32_t a2,
                                         uint32_t a3, uint32_t b0, uint32_t b1) {
    asm volatile(
        "mma.sync.aligned.m16n8k8.row.col.f32.tf32.tf32.f32 "
        "{%0,%1,%2,%3}, {%4,%5,%6,%7}, {%8,%9}, {%0,%1,%2,%3};"
        : "+f"(c0), "+f"(c1), "+f"(c2), "+f"(c3)
        : "r"(a0), "r"(a1), "r"(a2), "r"(a3), "r"(b0), "r"(b1));
}

// ---------------------------------------------------------------------------
// prep kernel: B -> tf32 global scratch; per-head 7x7 contractions
// ---------------------------------------------------------------------------
__global__ __launch_bounds__(512) void prep_kernel(
    const float* __restrict__ Wfc, const float* __restrict__ Wq,
    const float* __restrict__ Wk,  const float* __restrict__ Wv,
    const float* __restrict__ Wo)
{
    const int idx = blockIdx.x * 512 + threadIdx.x;
    if (idx < F_DIM * 8) {
        const int k = idx >> 3, n = idx & 7;
        const float v = (n < C) ? Wfc[n * F_DIM + k] : 0.f;
        g_Btf[idx] = to_tf32(v);
    }
    if (blockIdx.x == 0 && threadIdx.x < N_HEADS * C * C) {
        const int i = threadIdx.x;
        const int h = i / (C * C);
        const int rem = i - h * (C * C);
        const int c = rem / C, c2 = rem - c * C;
        const float* wq = Wq + (h * 64) * C + c;
        const float* wk = Wk + (h * 64) * C + c2;
        const float* wo = Wo + c * (N_HEADS * 64) + h * 64;
        const float* wv = Wv + (h * 64) * C + c2;
        float sa = 0.f, sb = 0.f;
#pragma unroll 8
        for (int d = 0; d < 64; ++d) {
            sa = fmaf(wq[d * C], wk[d * C], sa);
            sb = fmaf(wo[d],     wv[d * C], sb);
        }
        g_cA[h * 56 + c * 8 + c2] = sa;
        g_cB[h * 56 + c * 8 + c2] = sb;
    }
}

extern __shared__ float dyn_raw[];

__global__ __launch_bounds__(THREADS, 2) void fused_kernel(
    const __grid_constant__ CUtensorMap tmapA,
    const float* __restrict__ x,
    const float* __restrict__ ln1g, const float* __restrict__ ln1b,
    const float* __restrict__ Wff1, const float* __restrict__ Wff2,
    const float* __restrict__ ln2g, const float* __restrict__ ln2b,
    float* __restrict__ out)
{
    __shared__ float s_feats[ROWS][8];
    __shared__ float s_feas[FPB][8];
    __shared__ float sA[N_HEADS * C * 8];
    __shared__ float sB[N_HEADS * C * 8];
    __shared__ float sF1[D_FF * 9];
    __shared__ float sF2[C * 65];
    __shared__ __align__(8) unsigned long long m_fill[NBUF];
    __shared__ __align__(8) unsigned long long m_cons[NBUF];

    uintptr_t praw = (uintptr_t)dyn_raw;
    float* ring = (float*)((praw + 1023) & ~(uintptr_t)1023);
    float* sN = ring;                  // aliases (ring dead post-GEMM)
    float* sP = ring + NP_F;
    float* comb = ring;                // combine buffer (pre-N/P)

    const int tid  = threadIdx.x;
    const int lane = tid & 31;
    const int wid  = tid >> 5;
    const int t0   = blockIdx.x * FPB;

    if (tid < NBUF) {
        mbar_init(smem_u32(&m_fill[tid]), 1);
        mbar_init(smem_u32(&m_cons[tid]), CWARPS);
    }

    // ---- staging ----
    for (int i = tid; i < ROWS * C; i += THREADS) {
        const int r = i / C, c = i - r * C;
        const int g = t0 - (LEN_Q - 1) + r;
        s_feats[r][c] = (g >= 0) ? x[c * T_FRAMES + g] : 0.f;
    }
    for (int i = tid; i < N_HEADS * C * 8; i += THREADS) {
        sA[i] = g_cA[i];
        sB[i] = g_cB[i];
    }
    for (int i = tid; i < D_FF * C; i += THREADS) {
        const int j = i / C, c = i - j * C;
        sF1[j * 9 + c] = Wff1[i];
    }
    for (int i = tid; i < C * D_FF; i += THREADS) {
        const int c = i / D_FF, j = i - c * D_FF;
        sF2[c * 65 + j] = Wff2[i];
    }
    __syncthreads();

    const uint32_t ring_u32 = smem_u32(ring);

    float c0 = 0.f, c1 = 0.f, c2 = 0.f, c3 = 0.f;

    if (wid == CWARPS) {
        // ================= producer warp =================
        if (lane == 0) {
            for (int g = 0; g < CHUNKS; ++g) {
                const int b = g & (NBUF - 1);
                if (g >= NBUF)
                    mbar_wait_parity(smem_u32(&m_cons[b]), ((g >> 2) + 1) & 1);
                mbar_expect_tx(smem_u32(&m_fill[b]), CH_BYTES);
                tma_2d(ring_u32 + b * CH_BYTES, &tmapA, g * KC, t0,
                       smem_u32(&m_fill[b]));
            }
        }
    } else {
        // ============ compute warps: paired tf32 MMA ============
        // warp pair (w, w+4) shares frames tile=(w&3); w handles kh=w>>2 half.
        const int tile = wid & 3;
        const int kh   = wid >> 2;         // 0 or 1 (K-half within chunk)
        const int gq   = lane >> 2;
        const int tq   = lane & 3;
        const int f0   = tile * 16 + gq;   // rows f0, f0+8 within chunk
        const uint32_t xm = (uint32_t)((f0 & 7) << 4);   // SW128 mask (gq<8)
        const char* rb0 = (const char*)ring + f0 * 128;
        const char* rb1 = rb0 + 8 * 128;
        const uint32_t* gB = g_Btf + gq;

        for (int g = 0; g < CHUNKS; ++g) {
            const int b = g & (NBUF - 1);
            mbar_wait_parity(smem_u32(&m_fill[b]), (g >> 2) & 1);
            const uint32_t cb = b * CH_BYTES;
#pragma unroll
            for (int s = 0; s < 2; ++s) {
                const int ks = kh * 2 + s;
                const uint32_t k0 = (uint32_t)(ks * 32 + tq * 4);
                const uint32_t o0 = cb + (k0 ^ xm);
                const uint32_t o1 = cb + ((k0 + 16) ^ xm);
                const uint32_t a0 = to_tf32(*(const float*)(rb0 + o0));
                const uint32_t a1 = to_tf32(*(const float*)(rb1 + o0));
                const uint32_t a2 = to_tf32(*(const float*)(rb0 + o1));
                const uint32_t a3 = to_tf32(*(const float*)(rb1 + o1));
                const int kidx = g * KC + ks * 8 + tq;
                const uint32_t b0 = __ldg(gB + kidx * 8);
                const uint32_t b1 = __ldg(gB + (kidx + 4) * 8);
                mma_tf32(c0, c1, c2, c3, a0, a1, a2, a3, b0, b1);
            }
            if (lane == 0) mbar_arrive(smem_u32(&m_cons[b]));
        }
    }
    __syncthreads();                 // GEMM done; ring reusable

    // ---- combine warp pairs: (w) += (w+4), tanh -> s_feas ----
    if (wid >= 4 && wid < 8) {
        const int idx = (wid - 4) * 128 + lane * 4;
        comb[idx]     = c0;
        comb[idx + 1] = c1;
        comb[idx + 2] = c2;
        comb[idx + 3] = c3;
    }
    __syncthreads();
    if (wid < 4) {
        const int idx = wid * 128 + lane * 4;
        c0 += comb[idx];
        c1 += comb[idx + 1];
        c2 += comb[idx + 2];
        c3 += comb[idx + 3];
        const int gq = lane >> 2, tq = lane & 3;
        const int fr0 = wid * 16 + gq;
        const int cc  = tq * 2;
        s_feas[fr0][cc] = tanhf(c0);
        if (cc + 1 < C) s_feas[fr0][cc + 1] = tanhf(c1);
        s_feas[fr0 + 8][cc] = tanhf(c2);
        if (cc + 1 < C) s_feas[fr0 + 8][cc + 1] = tanhf(c3);
    }
    __syncthreads();                 // comb reads done; s_feas ready

    // ---- N[r,h,c] = (A_h feat_r)[c],  P[r,h,c] = (B_h feat_r)[c] ----
    for (int i = tid; i < ROWS * N_HEADS * C; i += THREADS) {
        const int r = i / (N_HEADS * C);
        const int j = i - r * (N_HEADS * C);
        const int h = j / C, c = j - h * C;
        float sn = 0.f, sp = 0.f;
        const int ab = h * 56 + c * 8;
#pragma unroll
        for (int c2i = 0; c2i < C; ++c2i) {
            const float fv = s_feats[r][c2i];
            sn = fmaf(sA[ab + c2i], fv, sn);
            sp = fmaf(sB[ab + c2i], fv, sp);
        }
        sN[r * NSTR + h * 8 + c] = sn;
        sP[r * NSTR + h * 8 + c] = sp;
    }
    __syncthreads();

    // ---- attention (online softmax) + LN1 + FFN + LN2 ----
    if (tid < FPB * N_HEADS) {
        const int f = tid >> 2;
        const int h = tid & 3;
        const int t = t0 + f;

        float ff[C];
#pragma unroll
        for (int c = 0; c < C; ++c) ff[c] = s_feas[f][c];

        const float* nb = sN + f * NSTR + h * 8;
        const float* pb = sP + f * NSTR + h * 8;

        float m = -1e30f, den = 0.f;
        float o[C];
#pragma unroll
        for (int c = 0; c < C; ++c) o[c] = 0.f;

#pragma unroll
        for (int l = 0; l < LEN_Q; ++l) {
            const float* nr = nb + l * NSTR;
            float s = ff[0] * nr[0];
#pragma unroll
            for (int c = 1; c < C; ++c) s = fmaf(ff[c], nr[c], s);
            s *= 0.125f;
            const float mn = fmaxf(m, s);
            const float corr = __expf(m - mn);
            const float wgt = __expf(s - mn);
            den = den * corr + wgt;
            const float* pr = pb + l * NSTR;
#pragma unroll
            for (int c = 0; c < C; ++c)
                o[c] = fmaf(o[c], corr, wgt * pr[c]);
            m = mn;
        }
        const float inv = 1.f / den;
#pragma unroll
        for (int c = 0; c < C; ++c) o[c] *= inv;

#pragma unroll
        for (int c = 0; c < C; ++c) {
            o[c] += __shfl_xor_sync(0xffffffffu, o[c], 1);
            o[c] += __shfl_xor_sync(0xffffffffu, o[c], 2);
        }

        float res[C];
        float mu = 0.f;
#pragma unroll
        for (int c = 0; c < C; ++c) { res[c] = o[c] + ff[c]; mu += res[c]; }
        mu *= (1.f / C);
        float var = 0.f;
#pragma unroll
        for (int c = 0; c < C; ++c) { const float dv = res[c] - mu; var += dv * dv; }
        var *= (1.f / C);
        float rs = rsqrtf(var + 1e-5f);
#pragma unroll
        for (int c = 0; c < C; ++c) res[c] = (res[c] - mu) * rs * ln1g[c] + ln1b[c];

        float y[C];
#pragma unroll
        for (int c = 0; c < C; ++c) y[c] = 0.f;
        const int j0 = h * 16;
#pragma unroll
        for (int jj = 0; jj < 16; ++jj) {
            const int j = j0 + jj;
            float a = 0.f;
#pragma unroll
            for (int c = 0; c < C; ++c) a = fmaf(res[c], sF1[j * 9 + c], a);
            a = fmaxf(a, 0.f);
#pragma unroll
            for (int c = 0; c < C; ++c) y[c] = fmaf(a, sF2[c * 65 + j], y[c]);
        }
#pragma unroll
        for (int c = 0; c < C; ++c) {
            y[c] += __shfl_xor_sync(0xffffffffu, y[c], 1);
            y[c] += __shfl_xor_sync(0xffffffffu, y[c], 2);
        }

        if (h == 0) {
            float z[C];
            mu = 0.f;
#pragma unroll
            for (int c = 0; c < C; ++c) { z[c] = y[c] + res[c]; mu += z[c]; }
            mu *= (1.f / C);
            var = 0.f;
#pragma unroll
            for (int c = 0; c < C; ++c) { const float dv = z[c] - mu; var += dv * dv; }
            var *= (1.f / C);
            rs = rsqrtf(var + 1e-5f);
#pragma unroll
            for (int c = 0; c < C; ++c)
                out[t * C + c] = (z[c] - mu) * rs * ln2g[c] + ln2b[c];
        }
    }
}

// ---------------------------------------------------------------------------
typedef CUresult (*EncodeFn)(
    CUtensorMap*, CUtensorMapDataType, cuuint32_t, void*,
    const cuuint64_t*, const cuuint64_t*, const cuuint32_t*, const cuuint32_t*,
    CUtensorMapInterleave, CUtensorMapSwizzle, CUtensorMapL2promotion,
    CUtensorMapFloatOOBfill);

extern "C" void kernel_launch(void* const* d_in, const int* in_sizes, int n_in,
                              void* d_out, int out_size) {
    const float* x    = (const float*)d_in[0];
    const float* LF   = (const float*)d_in[1];
    const float* Wfc  = (const float*)d_in[2];
    const float* Wq   = (const float*)d_in[3];
    const float* Wk   = (const float*)d_in[4];
    const float* Wv   = (const float*)d_in[5];
    const float* Wo   = (const float*)d_in[6];
    const float* ln1g = (const float*)d_in[7];
    const float* ln1b = (const float*)d_in[8];
    const float* Wff1 = (const float*)d_in[9];
    const float* Wff2 = (const float*)d_in[10];
    const float* ln2g = (const float*)d_in[11];
    const float* ln2b = (const float*)d_in[12];
    float* out = (float*)d_out;

    static EncodeFn enc = nullptr;
    if (!enc) {
        void* fp = nullptr;
        cudaDriverEntryPointQueryResult st;
        cudaGetDriverEntryPointByVersion("cuTensorMapEncodeTiled", &fp, 12000,
                                         cudaEnableDefault, &st);
        enc = (EncodeFn)fp;
    }

    CUtensorMap tmapA;
    cuuint64_t dims[2]    = {F_DIM, T_FRAMES};
    cuuint64_t strides[1] = {F_DIM * sizeof(float)};
    cuuint32_t box[2]     = {KC, FPB};
    cuuint32_t es[2]      = {1, 1};
    enc(&tmapA, CU_TENSOR_MAP_DATA_TYPE_FLOAT32, 2, (void*)LF,
        dims, strides, box, es,
        CU_TENSOR_MAP_INTERLEAVE_NONE, CU_TENSOR_MAP_SWIZZLE_128B,
        CU_TENSOR_MAP_L2_PROMOTION_L2_128B, CU_TENSOR_MAP_FLOAT_OOB_FILL_NONE);

    cudaFuncSetAttribute(fused_kernel,
                         cudaFuncAttributeMaxDynamicSharedMemorySize, DYN_BYTES);

    prep_kernel<<<(F_DIM * 8 + 511) / 512, 512>>>(Wfc, Wq, Wk, Wv, Wo);
    fused_kernel<<<T_FRAMES / FPB, THREADS, DYN_BYTES>>>(
        tmapA, x, ln1g, ln1b, Wff1, Wff2, ln2g, ln2b, out);
}

// round 16
// speedup vs baseline: 1.4671x; 1.4671x over previous
#include <cuda_runtime.h>
#include <math.h>
#include <stdint.h>

#define T_FRAMES 16384
#define C        7
#define F_DIM    2048
#define LEN_Q    30
#define N_HEADS  4
#define D_FF     64

#define NBLOCKS  296                   // 2 per SM, exactly one wave
#define BIG_N    200                   // blocks with 56 frames (rest: 54)
#define FPB_MAX  56
#define GRP      2                     // frames per TMA group
#define NBUF     4                     // ring depth
#define GBYTES   (GRP * F_DIM * 4)     // 16384 B per group
#define GFLOATS  (GRP * F_DIM)         // 4096
#define ROWS_MAX (FPB_MAX + LEN_Q - 1) // 85
#define NSTR     33                    // N/P row stride -> conflict-free perm
#define NP_MAX   (ROWS_MAX * NSTR)     // 2805

#define THREADS  256

#define RED_FS   65                    // per-frame red stride (8 warps * 8 + 1)
#define RED_F    (FPB_MAX * RED_FS)    // 3640 floats
#define BUF_F    (NBUF * GFLOATS)      // 16384 floats
#define DYN_F    (RED_F + BUF_F)       // 20024 floats = 80096 B

typedef unsigned long long u64;

__device__ __forceinline__ u64 fma2(u64 a, u64 b, u64 c) {
    u64 d;
    asm("fma.rn.f32x2 %0, %1, %2, %3;" : "=l"(d) : "l"(a), "l"(b), "l"(c));
    return d;
}
__device__ __forceinline__ float pairsum(u64 a) {
    const float lo = __uint_as_float((unsigned)(a & 0xffffffffull));
    const float hi = __uint_as_float((unsigned)(a >> 32));
    return lo + hi;
}
__device__ __forceinline__ uint32_t smem_u32(const void* p) {
    uint32_t a;
    asm("{ .reg .u64 t; cvta.to.shared.u64 t, %1; cvt.u32.u64 %0, t; }"
        : "=r"(a) : "l"(p));
    return a;
}
__device__ __forceinline__ void mbar_init(uint32_t mbar, uint32_t cnt) {
    asm volatile("mbarrier.init.shared.b64 [%0], %1;" :: "r"(mbar), "r"(cnt) : "memory");
}
__device__ __forceinline__ void mbar_expect_tx(uint32_t mbar, uint32_t bytes) {
    asm volatile("mbarrier.arrive.expect_tx.shared.b64 _, [%0], %1;"
                 :: "r"(mbar), "r"(bytes) : "memory");
}
__device__ __forceinline__ void mbar_wait_parity(uint32_t mbar, uint32_t ph) {
    asm volatile(
        "{\n\t"
        ".reg .pred P;\n\t"
        "WAIT_%=:\n\t"
        "mbarrier.try_wait.parity.acquire.cta.shared::cta.b64 P, [%0], %1, 0x989680;\n\t"
        "@P bra.uni DONE_%=;\n\t"
        "bra.uni WAIT_%=;\n\t"
        "DONE_%=:\n\t"
        "}"
        :: "r"(mbar), "r"(ph) : "memory");
}
__device__ __forceinline__ void tma_bulk_1d(uint32_t dst_smem, const void* src,
                                            uint32_t bytes, uint32_t mbar) {
    asm volatile(
        "cp.async.bulk.shared::cta.global.mbarrier::complete_tx::bytes "
        "[%0], [%1], %2, [%3];"
        :: "r"(dst_smem), "l"(src), "r"(bytes), "r"(mbar) : "memory");
}

extern __shared__ float dyn[];   // [red 3640][buf0..3, 4096 each]

__global__ __launch_bounds__(THREADS, 2) void fused_kernel(
    const float* __restrict__ x,    const float* __restrict__ LF,
    const float* __restrict__ Wfc,  const float* __restrict__ Wq,
    const float* __restrict__ Wk,   const float* __restrict__ Wv,
    const float* __restrict__ Wo,
    const float* __restrict__ ln1g, const float* __restrict__ ln1b,
    const float* __restrict__ Wff1, const float* __restrict__ Wff2,
    const float* __restrict__ ln2g, const float* __restrict__ ln2b,
    float* __restrict__ out)
{
    __shared__ float s_feats[ROWS_MAX][8];
    __shared__ float s_feas[FPB_MAX][8];
    __shared__ float sA[N_HEADS][C][8];
    __shared__ float sB[N_HEADS][C][8];
    __shared__ float sF1[D_FF * 9];
    __shared__ float sF2[C * 65];
    __shared__ __align__(8) unsigned long long m_fill[NBUF];

    float* red = dyn;
    float* ring = dyn + RED_F;
    // after the FC loop the ring+red region is dead; alias N/P there
    float* sN = dyn;
    float* sP = dyn + NP_MAX;

    const int tid  = threadIdx.x;
    const int lane = tid & 31;
    const int warp = tid >> 5;
    const int bid  = blockIdx.x;

    // balanced split: 200 blocks x 56 frames + 96 blocks x 54 frames = 16384
    const int big  = (bid < BIG_N);
    const int len  = big ? 56 : 54;
    const int t0   = big ? bid * 56 : BIG_N * 56 + (bid - BIG_N) * 54;
    const int ngrp = len >> 1;                 // 28 or 27
    const int rows = len + LEN_Q - 1;

    if (tid < NBUF) mbar_init(smem_u32(&m_fill[tid]), 1);

    // ---- early staging (hidden under the stream) ----
    for (int i = tid; i < rows * C; i += THREADS) {
        const int r = i / C, c = i - r * C;
        const int g = t0 - (LEN_Q - 1) + r;
        s_feats[r][c] = (g >= 0) ? x[c * T_FRAMES + g] : 0.f;
    }
    for (int i = tid; i < D_FF * C; i += THREADS) {
        const int j = i / C, c = i - j * C;
        sF1[j * 9 + c] = Wff1[i];
    }
    for (int i = tid; i < C * D_FF; i += THREADS) {
        const int c = i / D_FF, j = i - c * D_FF;
        sF2[c * 65 + j] = Wff2[i];
    }

    const char* lf_base =
        reinterpret_cast<const char*>(LF) + (size_t)t0 * F_DIM * 4;

    // ---- W_fc in registers as packed f32x2 pairs ----
    ulonglong2 w0[C], w1[C];
#pragma unroll
    for (int c = 0; c < C; ++c) {
        const ulonglong2* wr = reinterpret_cast<const ulonglong2*>(Wfc + c * F_DIM);
        w0[c] = wr[tid];
        w1[c] = wr[tid + 256];
    }

    __syncthreads();                 // mbarrier init + staging ordering

    if (tid == 224) {                // warp 7 lane 0: prime all 4 ring slots
#pragma unroll
        for (int b = 0; b < NBUF; ++b) {
            mbar_expect_tx(smem_u32(&m_fill[b]), GBYTES);
            tma_bulk_1d(smem_u32(ring + b * GFLOATS),
                        lf_base + (size_t)b * GBYTES, GBYTES,
                        smem_u32(&m_fill[b]));
        }
    }

    // warp-level split-reduce of an 8-channel partial vector; lane (4c..4c+3)
    // ends holding channel c's warp sum; lane&3==0 stores it.
    auto reduceStore = [&](float (&p)[8], int f) {
        float q[4];
#pragma unroll
        for (int k = 0; k < 4; ++k) {
            const float send = (lane & 16) ? p[k] : p[k + 4];
            const float o = __shfl_xor_sync(0xffffffffu, send, 16);
            q[k] = ((lane & 16) ? p[k + 4] : p[k]) + o;
        }
        float r2[2];
#pragma unroll
        for (int k = 0; k < 2; ++k) {
            const float send = (lane & 8) ? q[k] : q[k + 2];
            const float o = __shfl_xor_sync(0xffffffffu, send, 8);
            r2[k] = ((lane & 8) ? q[k + 2] : q[k]) + o;
        }
        {
            const float send = (lane & 4) ? r2[0] : r2[1];
            const float o = __shfl_xor_sync(0xffffffffu, send, 4);
            r2[0] = ((lane & 4) ? r2[1] : r2[0]) + o;
        }
        r2[0] += __shfl_xor_sync(0xffffffffu, r2[0], 2);
        r2[0] += __shfl_xor_sync(0xffffffffu, r2[0], 1);

        const int c = (lane >> 2) & 7;
        if ((lane & 3) == 0 && c < C)
            red[f * RED_FS + warp * 8 + c] = r2[0];
    };

    // ---- FC stream, software-pipelined reduce (chain of g-1 hides under g) --
    float pv[GRP][8];                // previous group's partials
    for (int g = 0; g < ngrp; ++g) {
        const int b = g & (NBUF - 1);
        const float* bufb = ring + b * GFLOATS;
        mbar_wait_parity(smem_u32(&m_fill[b]), (g >> 2) & 1);

        // issue loads for group g first (latency hides under prev reduce)
        ulonglong2 aa[GRP], bb[GRP];
#pragma unroll
        for (int j = 0; j < GRP; ++j) {
            const ulonglong2* fb =
                reinterpret_cast<const ulonglong2*>(bufb + j * F_DIM);
            aa[j] = fb[tid];
            bb[j] = fb[tid + 256];
        }

        // reduce PREVIOUS group while loads are in flight
        if (g > 0) {
#pragma unroll
            for (int j = 0; j < GRP; ++j)
                reduceStore(pv[j], (g - 1) * GRP + j);
        }

        // fma for group g -> pv
#pragma unroll
        for (int j = 0; j < GRP; ++j) {
#pragma unroll
            for (int c = 0; c < C; ++c) {
                u64 acc = 0ull;
                acc = fma2(aa[j].x, w0[c].x, acc);
                acc = fma2(aa[j].y, w0[c].y, acc);
                acc = fma2(bb[j].x, w1[c].x, acc);
                acc = fma2(bb[j].y, w1[c].y, acc);
                pv[j][c] = pairsum(acc);
            }
            pv[j][7] = 0.f;
        }

        __syncthreads();             // all warps done reading buffer b
        if (tid == 224 && g + NBUF < ngrp) {
            const uint32_t mb = smem_u32(&m_fill[b]);
            mbar_expect_tx(mb, GBYTES);
            tma_bulk_1d(smem_u32(ring + b * GFLOATS),
                        lf_base + (size_t)(g + NBUF) * GBYTES, GBYTES, mb);
        }
    }
    // drain the last group's reduce
#pragma unroll
    for (int j = 0; j < GRP; ++j)
        reduceStore(pv[j], (ngrp - 1) * GRP + j);
    __syncthreads();                 // red complete

    // ---- feas final reduce (8 warp-sums) + tanh ----
    for (int i = tid; i < len * C; i += THREADS) {
        const int f = i / C, c = i - f * C;
        float s = 0.f;
        const int base = f * RED_FS + c;
#pragma unroll
        for (int w = 0; w < 8; ++w) s += red[base + w * 8];
        s_feas[f][c] = tanhf(s);
    }

    // ---- per-head 7x7 contractions A_h = Wq^T Wk, B_h = Wo Wv ----
    if (tid < N_HEADS * C * C) {
        const int h = tid / (C * C);
        const int rem = tid - h * (C * C);
        const int c = rem / C, c2 = rem - c * C;
        const float* wq = Wq + (h * 64) * C + c;
        const float* wk = Wk + (h * 64) * C + c2;
        const float* wo = Wo + c * (N_HEADS * 64) + h * 64;
        const float* wv = Wv + (h * 64) * C + c2;
        float sa = 0.f, sb = 0.f;
#pragma unroll 8
        for (int d = 0; d < 64; ++d) {
            sa = fmaf(wq[d * C], wk[d * C], sa);
            sb = fmaf(wo[d],     wv[d * C], sb);
        }
        sA[h][c][c2] = sa;
        sB[h][c][c2] = sb;
    }
    __syncthreads();                 // red read done; ring+red dead -> sN/sP

    // ---- N[r,h,c] = (A_h feat_r)[c],  P[r,h,c] = (B_h feat_r)[c] ----
    for (int i = tid; i < rows * N_HEADS * C; i += THREADS) {
        const int r = i / (N_HEADS * C);
        const int j = i - r * (N_HEADS * C);
        const int h = j / C, c = j - h * C;
        float sn = 0.f, sp = 0.f;
#pragma unroll
        for (int c2 = 0; c2 < C; ++c2) {
            const float fv = s_feats[r][c2];
            sn = fmaf(sA[h][c][c2], fv, sn);
            sp = fmaf(sB[h][c][c2], fv, sp);
        }
        sN[r * NSTR + h * 8 + c] = sn;
        sP[r * NSTR + h * 8 + c] = sp;
    }
    __syncthreads();

    // ---- attention + LN1 + FFN + LN2 (thread = frame x head) ----
    if (tid < len * N_HEADS) {
        const int f = tid >> 2;
        const int h = tid & 3;
        const int t = t0 + f;

        float ff[C];
#pragma unroll
        for (int c = 0; c < C; ++c) ff[c] = s_feas[f][c];

        float sc[LEN_Q];
        const float* nb = sN + f * NSTR + h * 8;
#pragma unroll
        for (int l = 0; l < LEN_Q; ++l) {
            const float* nr = nb + l * NSTR;
            float s = ff[0] * nr[0];
#pragma unroll
            for (int c = 1; c < C; ++c) s = fmaf(ff[c], nr[c], s);
            sc[l] = s * 0.125f;
        }

        float mx = sc[0];
#pragma unroll
        for (int l = 1; l < LEN_Q; ++l) mx = fmaxf(mx, sc[l]);
        float den = 0.f;
#pragma unroll
        for (int l = 0; l < LEN_Q; ++l) { sc[l] = __expf(sc[l] - mx); den += sc[l]; }
        const float inv = 1.f / den;
#pragma unroll
        for (int l = 0; l < LEN_Q; ++l) sc[l] *= inv;

        float o[C];
#pragma unroll
        for (int c = 0; c < C; ++c) o[c] = 0.f;
        const float* pb = sP + f * NSTR + h * 8;
#pragma unroll
        for (int l = 0; l < LEN_Q; ++l) {
            const float w = sc[l];
            const float* pr = pb + l * NSTR;
#pragma unroll
            for (int c = 0; c < C; ++c) o[c] = fmaf(w, pr[c], o[c]);
        }
#pragma unroll
        for (int c = 0; c < C; ++c) {
            o[c] += __shfl_xor_sync(0xffffffffu, o[c], 1);
            o[c] += __shfl_xor_sync(0xffffffffu, o[c], 2);
        }

        float res[C];
        float mu = 0.f;
#pragma unroll
        for (int c = 0; c < C; ++c) { res[c] = o[c] + ff[c]; mu += res[c]; }
        mu *= (1.f / C);
        float var = 0.f;
#pragma unroll
        for (int c = 0; c < C; ++c) { const float dv = res[c] - mu; var += dv * dv; }
        var *= (1.f / C);
        float rs = rsqrtf(var + 1e-5f);
#pragma unroll
        for (int c = 0; c < C; ++c) res[c] = (res[c] - mu) * rs * ln1g[c] + ln1b[c];

        float y[C];
#pragma unroll
        for (int c = 0; c < C; ++c) y[c] = 0.f;
        const int j0 = h * 16;
#pragma unroll
        for (int jj = 0; jj < 16; ++jj) {
            const int j = j0 + jj;
            float a = 0.f;
#pragma unroll
            for (int c = 0; c < C; ++c) a = fmaf(res[c], sF1[j * 9 + c], a);
            a = fmaxf(a, 0.f);
#pragma unroll
            for (int c = 0; c < C; ++c) y[c] = fmaf(a, sF2[c * 65 + j], y[c]);
        }
#pragma unroll
        for (int c = 0; c < C; ++c) {
            y[c] += __shfl_xor_sync(0xffffffffu, y[c], 1);
            y[c] += __shfl_xor_sync(0xffffffffu, y[c], 2);
        }

        if (h == 0) {
            float z[C];
            mu = 0.f;
#pragma unroll
            for (int c = 0; c < C; ++c) { z[c] = y[c] + res[c]; mu += z[c]; }
            mu *= (1.f / C);
            var = 0.f;
#pragma unroll
            for (int c = 0; c < C; ++c) { const float dv = z[c] - mu; var += dv * dv; }
            var *= (1.f / C);
            rs = rsqrtf(var + 1e-5f);
#pragma unroll
            for (int c = 0; c < C; ++c)
                out[t * C + c] = (z[c] - mu) * rs * ln2g[c] + ln2b[c];
        }
    }
}

// ---------------------------------------------------------------------------
extern "C" void kernel_launch(void* const* d_in, const int* in_sizes, int n_in,
                              void* d_out, int out_size) {
    const float* x    = (const float*)d_in[0];
    const float* LF   = (const float*)d_in[1];
    const float* Wfc  = (const float*)d_in[2];
    const float* Wq   = (const float*)d_in[3];
    const float* Wk   = (const float*)d_in[4];
    const float* Wv   = (const float*)d_in[5];
    const float* Wo   = (const float*)d_in[6];
    const float* ln1g = (const float*)d_in[7];
    const float* ln1b = (const float*)d_in[8];
    const float* Wff1 = (const float*)d_in[9];
    const float* Wff2 = (const float*)d_in[10];
    const float* ln2g = (const float*)d_in[11];
    const float* ln2b = (const float*)d_in[12];
    float* out = (float*)d_out;

    const int dyn_bytes = DYN_F * (int)sizeof(float);   // 80096
    cudaFuncSetAttribute(fused_kernel,
                         cudaFuncAttributeMaxDynamicSharedMemorySize, dyn_bytes);

    fused_kernel<<<NBLOCKS, THREADS, dyn_bytes>>>(
        x, LF, Wfc, Wq, Wk, Wv, Wo, ln1g, ln1b,
        Wff1, Wff2, ln2g, ln2b, out);
}

// round 17
// speedup vs baseline: 1.4768x; 1.0066x over previous
#include <cuda_runtime.h>
#include <math.h>
#include <stdint.h>

#define T_FRAMES 16384
#define C        7
#define F_DIM    2048
#define LEN_Q    30
#define N_HEADS  4
#define D_FF     64

#define NBLOCKS  296                   // 2 per SM, exactly one wave
#define BIG_N    200                   // blocks with 56 frames (rest: 54)
#define FPB_MAX  56
#define GRP      2                     // frames per TMA group
#define NBUF     5                     // ring depth (4 groups in flight)
#define GBYTES   (GRP * F_DIM * 4)     // 16384 B per group
#define GFLOATS  (GRP * F_DIM)         // 4096
#define ROWS_MAX (FPB_MAX + LEN_Q - 1) // 85
#define NSTR     33                    // N/P row stride -> conflict-free perm
#define NP_MAX   (ROWS_MAX * NSTR)     // 2805

#define THREADS  256
#define CWARPS   8

#define RED_FS   65                    // per-frame red stride (8 warps * 8 + 1)
#define RED_F    (FPB_MAX * RED_FS)    // 3640 floats
#define BUF_F    (NBUF * GFLOATS)      // 20480 floats
#define DYN_F    (RED_F + BUF_F)       // 24120 floats = 96480 B

typedef unsigned long long u64;

__device__ __forceinline__ u64 fma2(u64 a, u64 b, u64 c) {
    u64 d;
    asm("fma.rn.f32x2 %0, %1, %2, %3;" : "=l"(d) : "l"(a), "l"(b), "l"(c));
    return d;
}
__device__ __forceinline__ float pairsum(u64 a) {
    const float lo = __uint_as_float((unsigned)(a & 0xffffffffull));
    const float hi = __uint_as_float((unsigned)(a >> 32));
    return lo + hi;
}
__device__ __forceinline__ uint32_t smem_u32(const void* p) {
    uint32_t a;
    asm("{ .reg .u64 t; cvta.to.shared.u64 t, %1; cvt.u32.u64 %0, t; }"
        : "=r"(a) : "l"(p));
    return a;
}
__device__ __forceinline__ void mbar_init(uint32_t mbar, uint32_t cnt) {
    asm volatile("mbarrier.init.shared.b64 [%0], %1;" :: "r"(mbar), "r"(cnt) : "memory");
}
__device__ __forceinline__ void mbar_arrive(uint32_t mbar) {
    asm volatile("mbarrier.arrive.release.cta.shared::cta.b64 _, [%0];"
                 :: "r"(mbar) : "memory");
}
__device__ __forceinline__ void mbar_expect_tx(uint32_t mbar, uint32_t bytes) {
    asm volatile("mbarrier.arrive.expect_tx.shared.b64 _, [%0], %1;"
                 :: "r"(mbar), "r"(bytes) : "memory");
}
__device__ __forceinline__ void mbar_wait_parity(uint32_t mbar, uint32_t ph) {
    asm volatile(
        "{\n\t"
        ".reg .pred P;\n\t"
        "WAIT_%=:\n\t"
        "mbarrier.try_wait.parity.acquire.cta.shared::cta.b64 P, [%0], %1, 0x989680;\n\t"
        "@P bra.uni DONE_%=;\n\t"
        "bra.uni WAIT_%=;\n\t"
        "DONE_%=:\n\t"
        "}"
        :: "r"(mbar), "r"(ph) : "memory");
}
__device__ __forceinline__ void tma_bulk_1d(uint32_t dst_smem, const void* src,
                                            uint32_t bytes, uint32_t mbar) {
    asm volatile(
        "cp.async.bulk.shared::cta.global.mbarrier::complete_tx::bytes "
        "[%0], [%1], %2, [%3];"
        :: "r"(dst_smem), "l"(src), "r"(bytes), "r"(mbar) : "memory");
}

extern __shared__ float dyn[];   // [red 3640][buf0..4, 4096 each]

__global__ __launch_bounds__(THREADS, 2) void fused_kernel(
    const float* __restrict__ x,    const float* __restrict__ LF,
    const float* __restrict__ Wfc,  const float* __restrict__ Wq,
    const float* __restrict__ Wk,   const float* __restrict__ Wv,
    const float* __restrict__ Wo,
    const float* __restrict__ ln1g, const float* __restrict__ ln1b,
    const float* __restrict__ Wff1, const float* __restrict__ Wff2,
    const float* __restrict__ ln2g, const float* __restrict__ ln2b,
    float* __restrict__ out)
{
    __shared__ float s_feats[ROWS_MAX][8];
    __shared__ float s_feas[FPB_MAX][8];
    __shared__ float sA[N_HEADS][C][8];
    __shared__ float sB[N_HEADS][C][8];
    __shared__ float sF1[D_FF * 9];
    __shared__ float sF2[C * 65];
    __shared__ __align__(8) unsigned long long m_fill[NBUF];
    __shared__ __align__(8) unsigned long long m_cons[NBUF];

    float* red = dyn;
    float* ring = dyn + RED_F;
    // after the FC loop the ring+red region is dead; alias N/P there
    float* sN = dyn;
    float* sP = dyn + NP_MAX;

    const int tid  = threadIdx.x;
    const int lane = tid & 31;
    const int warp = tid >> 5;
    const int bid  = blockIdx.x;

    // balanced split: 200 blocks x 56 frames + 96 blocks x 54 frames = 16384
    const int big  = (bid < BIG_N);
    const int len  = big ? 56 : 54;
    const int t0   = big ? bid * 56 : BIG_N * 56 + (bid - BIG_N) * 54;
    const int ngrp = len >> 1;                 // 28 or 27
    const int rows = len + LEN_Q - 1;

    if (tid < NBUF) {
        mbar_init(smem_u32(&m_fill[tid]), 1);
        mbar_init(smem_u32(&m_cons[tid]), CWARPS);
    }

    // ---- early staging (hidden under the stream) ----
    for (int i = tid; i < rows * C; i += THREADS) {
        const int r = i / C, c = i - r * C;
        const int g = t0 - (LEN_Q - 1) + r;
        s_feats[r][c] = (g >= 0) ? x[c * T_FRAMES + g] : 0.f;
    }
    for (int i = tid; i < D_FF * C; i += THREADS) {
        const int j = i / C, c = i - j * C;
        sF1[j * 9 + c] = Wff1[i];
    }
    for (int i = tid; i < C * D_FF; i += THREADS) {
        const int c = i / D_FF, j = i - c * D_FF;
        sF2[c * 65 + j] = Wff2[i];
    }

    const char* lf_base =
        reinterpret_cast<const char*>(LF) + (size_t)t0 * F_DIM * 4;

    // ---- W_fc in registers as packed f32x2 pairs ----
    ulonglong2 w0[C], w1[C];
#pragma unroll
    for (int c = 0; c < C; ++c) {
        const ulonglong2* wr = reinterpret_cast<const ulonglong2*>(Wfc + c * F_DIM);
        w0[c] = wr[tid];
        w1[c] = wr[tid + 256];
    }

    __syncthreads();                 // mbarrier init + staging ordering

    if (tid == 224) {                // warp 7 lane 0: prime all 5 ring slots
        for (int b = 0; b < NBUF; ++b) {
            mbar_expect_tx(smem_u32(&m_fill[b]), GBYTES);
            tma_bulk_1d(smem_u32(ring + b * GFLOATS),
                        lf_base + (size_t)b * GBYTES, GBYTES,
                        smem_u32(&m_fill[b]));
        }
    }

    // warp-level split-reduce of an 8-channel partial vector; lane (4c..4c+3)
    // ends holding channel c's warp sum; lane&3==0 stores it.
    auto reduceStore = [&](float (&p)[8], int f) {
        float q[4];
#pragma unroll
        for (int k = 0; k < 4; ++k) {
            const float send = (lane & 16) ? p[k] : p[k + 4];
            const float o = __shfl_xor_sync(0xffffffffu, send, 16);
            q[k] = ((lane & 16) ? p[k + 4] : p[k]) + o;
        }
        float r2[2];
#pragma unroll
        for (int k = 0; k < 2; ++k) {
            const float send = (lane & 8) ? q[k] : q[k + 2];
            const float o = __shfl_xor_sync(0xffffffffu, send, 8);
            r2[k] = ((lane & 8) ? q[k + 2] : q[k]) + o;
        }
        {
            const float send = (lane & 4) ? r2[0] : r2[1];
            const float o = __shfl_xor_sync(0xffffffffu, send, 4);
            r2[0] = ((lane & 4) ? r2[1] : r2[0]) + o;
        }
        r2[0] += __shfl_xor_sync(0xffffffffu, r2[0], 2);
        r2[0] += __shfl_xor_sync(0xffffffffu, r2[0], 1);

        const int c = (lane >> 2) & 7;
        if ((lane & 3) == 0 && c < C)
            red[f * RED_FS + warp * 8 + c] = r2[0];
    };

    // ---- FC stream: barrier-free (early-arrive consumed mbarriers) ----
    float pv[GRP][8];                // previous group's partials
    for (int g = 0; g < ngrp; ++g) {
        const int b = g % NBUF;
        const int ph = (g / NBUF) & 1;
        const float* bufb = ring + b * GFLOATS;
        mbar_wait_parity(smem_u32(&m_fill[b]), ph);

        // issue loads for group g first (latency hides under prev reduce)
        ulonglong2 aa[GRP], bb[GRP];
#pragma unroll
        for (int j = 0; j < GRP; ++j) {
            const ulonglong2* fb =
                reinterpret_cast<const ulonglong2*>(bufb + j * F_DIM);
            aa[j] = fb[tid];
            bb[j] = fb[tid + 256];
        }
        // loads retired into registers -> this warp is done with slot b
        if (lane == 0) mbar_arrive(smem_u32(&m_cons[b]));

        // producer: refill slot b with group g+NBUF once all warps loaded g
        if (tid == 224 && g + NBUF < ngrp) {
            mbar_wait_parity(smem_u32(&m_cons[b]), ph);
            const uint32_t mb = smem_u32(&m_fill[b]);
            mbar_expect_tx(mb, GBYTES);
            tma_bulk_1d(smem_u32(ring + b * GFLOATS),
                        lf_base + (size_t)(g + NBUF) * GBYTES, GBYTES, mb);
        }

        // reduce PREVIOUS group while this group's math is pending
        if (g > 0) {
#pragma unroll
            for (int j = 0; j < GRP; ++j)
                reduceStore(pv[j], (g - 1) * GRP + j);
        }

        // fma for group g -> pv
#pragma unroll
        for (int j = 0; j < GRP; ++j) {
#pragma unroll
            for (int c = 0; c < C; ++c) {
                u64 acc = 0ull;
                acc = fma2(aa[j].x, w0[c].x, acc);
                acc = fma2(aa[j].y, w0[c].y, acc);
                acc = fma2(bb[j].x, w1[c].x, acc);
                acc = fma2(bb[j].y, w1[c].y, acc);
                pv[j][c] = pairsum(acc);
            }
            pv[j][7] = 0.f;
        }
    }
    // drain the last group's reduce
#pragma unroll
    for (int j = 0; j < GRP; ++j)
        reduceStore(pv[j], (ngrp - 1) * GRP + j);
    __syncthreads();                 // all warps' red writes complete

    // ---- feas final reduce (8 warp-sums) + tanh ----
    for (int i = tid; i < len * C; i += THREADS) {
        const int f = i / C, c = i - f * C;
        float s = 0.f;
        const int base = f * RED_FS + c;
#pragma unroll
        for (int w = 0; w < 8; ++w) s += red[base + w * 8];
        s_feas[f][c] = tanhf(s);
    }

    // ---- per-head 7x7 contractions A_h = Wq^T Wk, B_h = Wo Wv ----
    if (tid < N_HEADS * C * C) {
        const int h = tid / (C * C);
        const int rem = tid - h * (C * C);
        const int c = rem / C, c2 = rem - c * C;
        const float* wq = Wq + (h * 64) * C + c;
        const float* wk = Wk + (h * 64) * C + c2;
        const float* wo = Wo + c * (N_HEADS * 64) + h * 64;
        const float* wv = Wv + (h * 64) * C + c2;
        float sa = 0.f, sb = 0.f;
#pragma unroll 8
        for (int d = 0; d < 64; ++d) {
            sa = fmaf(wq[d * C], wk[d * C], sa);
            sb = fmaf(wo[d],     wv[d * C], sb);
        }
        sA[h][c][c2] = sa;
        sB[h][c][c2] = sb;
    }
    __syncthreads();                 // red read done; ring+red dead -> sN/sP

    // ---- N[r,h,c] = (A_h feat_r)[c],  P[r,h,c] = (B_h feat_r)[c] ----
    for (int i = tid; i < rows * N_HEADS * C; i += THREADS) {
        const int r = i / (N_HEADS * C);
        const int j = i - r * (N_HEADS * C);
        const int h = j / C, c = j - h * C;
        float sn = 0.f, sp = 0.f;
#pragma unroll
        for (int c2 = 0; c2 < C; ++c2) {
            const float fv = s_feats[r][c2];
            sn = fmaf(sA[h][c][c2], fv, sn);
            sp = fmaf(sB[h][c][c2], fv, sp);
        }
        sN[r * NSTR + h * 8 + c] = sn;
        sP[r * NSTR + h * 8 + c] = sp;
    }
    __syncthreads();

    // ---- attention + LN1 + FFN + LN2 (thread = frame x head) ----
    if (tid < len * N_HEADS) {
        const int f = tid >> 2;
        const int h = tid & 3;
        const int t = t0 + f;

        float ff[C];
#pragma unroll
        for (int c = 0; c < C; ++c) ff[c] = s_feas[f][c];

        float sc[LEN_Q];
        const float* nb = sN + f * NSTR + h * 8;
#pragma unroll
        for (int l = 0; l < LEN_Q; ++l) {
            const float* nr = nb + l * NSTR;
            float s = ff[0] * nr[0];
#pragma unroll
            for (int c = 1; c < C; ++c) s = fmaf(ff[c], nr[c], s);
            sc[l] = s * 0.125f;
        }

        float mx = sc[0];
#pragma unroll
        for (int l = 1; l < LEN_Q; ++l) mx = fmaxf(mx, sc[l]);
        float den = 0.f;
#pragma unroll
        for (int l = 0; l < LEN_Q; ++l) { sc[l] = __expf(sc[l] - mx); den += sc[l]; }
        const float inv = 1.f / den;
#pragma unroll
        for (int l = 0; l < LEN_Q; ++l) sc[l] *= inv;

        float o[C];
#pragma unroll
        for (int c = 0; c < C; ++c) o[c] = 0.f;
        const float* pb = sP + f * NSTR + h * 8;
#pragma unroll
        for (int l = 0; l < LEN_Q; ++l) {
            const float w = sc[l];
            const float* pr = pb + l * NSTR;
#pragma unroll
            for (int c = 0; c < C; ++c) o[c] = fmaf(w, pr[c], o[c]);
        }
#pragma unroll
        for (int c = 0; c < C; ++c) {
            o[c] += __shfl_xor_sync(0xffffffffu, o[c], 1);
            o[c] += __shfl_xor_sync(0xffffffffu, o[c], 2);
        }

        float res[C];
        float mu = 0.f;
#pragma unroll
        for (int c = 0; c < C; ++c) { res[c] = o[c] + ff[c]; mu += res[c]; }
        mu *= (1.f / C);
        float var = 0.f;
#pragma unroll
        for (int c = 0; c < C; ++c) { const float dv = res[c] - mu; var += dv * dv; }
        var *= (1.f / C);
        float rs = rsqrtf(var + 1e-5f);
#pragma unroll
        for (int c = 0; c < C; ++c) res[c] = (res[c] - mu) * rs * ln1g[c] + ln1b[c];

        float y[C];
#pragma unroll
        for (int c = 0; c < C; ++c) y[c] = 0.f;
        const int j0 = h * 16;
#pragma unroll
        for (int jj = 0; jj < 16; ++jj) {
            const int j = j0 + jj;
            float a = 0.f;
#pragma unroll
            for (int c = 0; c < C; ++c) a = fmaf(res[c], sF1[j * 9 + c], a);
            a = fmaxf(a, 0.f);
#pragma unroll
            for (int c = 0; c < C; ++c) y[c] = fmaf(a, sF2[c * 65 + j], y[c]);
        }
#pragma unroll
        for (int c = 0; c < C; ++c) {
            y[c] += __shfl_xor_sync(0xffffffffu, y[c], 1);
            y[c] += __shfl_xor_sync(0xffffffffu, y[c], 2);
        }

        if (h == 0) {
            float z[C];
            mu = 0.f;
#pragma unroll
            for (int c = 0; c < C; ++c) { z[c] = y[c] + res[c]; mu += z[c]; }
            mu *= (1.f / C);
            var = 0.f;
#pragma unroll
            for (int c = 0; c < C; ++c) { const float dv = z[c] - mu; var += dv * dv; }
            var *= (1.f / C);
            rs = rsqrtf(var + 1e-5f);
#pragma unroll
            for (int c = 0; c < C; ++c)
                out[t * C + c] = (z[c] - mu) * rs * ln2g[c] + ln2b[c];
        }
    }
}

// ---------------------------------------------------------------------------
extern "C" void kernel_launch(void* const* d_in, const int* in_sizes, int n_in,
                              void* d_out, int out_size) {
    const float* x    = (const float*)d_in[0];
    const float* LF   = (const float*)d_in[1];
    const float* Wfc  = (const float*)d_in[2];
    const float* Wq   = (const float*)d_in[3];
    const float* Wk   = (const float*)d_in[4];
    const float* Wv   = (const float*)d_in[5];
    const float* Wo   = (const float*)d_in[6];
    const float* ln1g = (const float*)d_in[7];
    const float* ln1b = (const float*)d_in[8];
    const float* Wff1 = (const float*)d_in[9];
    const float* Wff2 = (const float*)d_in[10];
    const float* ln2g = (const float*)d_in[11];
    const float* ln2b = (const float*)d_in[12];
    float* out = (float*)d_out;

    const int dyn_bytes = DYN_F * (int)sizeof(float);   // 96480
    cudaFuncSetAttribute(fused_kernel,
                         cudaFuncAttributeMaxDynamicSharedMemorySize, dyn_bytes);

    fused_kernel<<<NBLOCKS, THREADS, dyn_bytes>>>(
        x, LF, Wfc, Wq, Wk, Wv, Wo, ln1g, ln1b,
        Wff1, Wff2, ln2g, ln2b, out);
}